// round 12
// baseline (speedup 1.0000x reference)
#include <cuda_runtime.h>
#include <cuda_fp16.h>
#include <cstdint>

// ---------------------------------------------------------------------------
// LSTM cell, fused, sm_103 plain target (no tcgen05).
// R10 = R9 resubmitted verbatim (R9 bench was an infra failure: the GB300
// container died twice before running; no measurement was taken).
// R9 theory under test: R8 (CTA 128x128, 4 warps of 64x64, 3 CTAs/SM,
// 3-stage cp.async) + software-pipelined B fragments (double-buffered
// n16-slices) to cover the LDSM->HMMA latency chain that held tensor
// occupancy at 57%.
//   A[b,k]  = fp16([X | h_old])   [65536, 768]
//   Bp[n,k] = fp16 packed, n=4h+g (gates interleaved along N)
//   G = A @ Bp^T  fp32 accum  ->  gates -> h_new, c_new  (fused epilogue)
// ---------------------------------------------------------------------------

#define BDIM 65536
#define HDIM 512
#define DIN  256
#define NTOT 2048
#define KTOT 768

#define BM 128
#define BN 128
#define BK 32
#define STAGES 3
#define NCH (KTOT / BK)            // 24

#define ROWB 80                    // 32 fp16 = 64B + 16B pad (ldmatrix safe)
#define A_BYTES (BM * ROWB)        // 10240
#define B_BYTES (BN * ROWB)        // 10240
#define STAGE_BYTES (A_BYTES + B_BYTES)           // 20480
#define SM_BIAS 0                                  // 512 B used
#define SM_AB   1024
#define SM_TOTAL (SM_AB + STAGES * STAGE_BYTES)    // 62464 (x3 CTAs = 187KB)

// epilogue overlay (stage area free by then): 128 rows x 32 h-cols, pad to 36
#define ROWE 36
#define HB_OFF SM_AB
#define CB_OFF (SM_AB + BM * ROWE * 4)             // 1024 + 18432

#define CONV_BLOCKS 49152
#define PACK_BLOCKS 1536

__device__ __half g_Apack[(size_t)BDIM * KTOT];    // 96 MB
__device__ __half g_Bp[(size_t)NTOT * KTOT];       // 3 MB
__device__ float  g_bias[NTOT];

// ---------------------------------------------------------------------------
__device__ __forceinline__ uint32_t smem_u32(const void* p) {
    uint32_t a;
    asm("{ .reg .u64 t; cvta.to.shared.u64 t, %1; cvt.u32.u64 %0, t; }"
        : "=r"(a) : "l"(p));
    return a;
}
__device__ __forceinline__ void cp16(uint32_t sa, const void* g) {
    asm volatile("cp.async.cg.shared.global [%0], [%1], 16;" :: "r"(sa), "l"(g));
}
#define LDSM4(r0, r1, r2, r3, a)                                              \
    asm volatile("ldmatrix.sync.aligned.m8n8.x4.shared.b16 {%0,%1,%2,%3}, [%4];" \
        : "=r"(r0), "=r"(r1), "=r"(r2), "=r"(r3) : "r"(a))

__device__ __forceinline__ void mma16816(float* c, const uint32_t* a, const uint32_t* b) {
    asm volatile(
        "mma.sync.aligned.m16n8k16.row.col.f32.f16.f16.f32 "
        "{%0,%1,%2,%3}, {%4,%5,%6,%7}, {%8,%9}, {%0,%1,%2,%3};"
        : "+f"(c[0]), "+f"(c[1]), "+f"(c[2]), "+f"(c[3])
        : "r"(a[0]), "r"(a[1]), "r"(a[2]), "r"(a[3]), "r"(b[0]), "r"(b[1]));
}
__device__ __forceinline__ float tanh_fast(float x) {
    float y;
    asm("tanh.approx.f32 %0, %1;" : "=f"(y) : "f"(x));
    return y;
}
__device__ __forceinline__ float sigmoid_fast(float x) {
    return fmaf(0.5f, tanh_fast(0.5f * x), 0.5f);
}

// ---------------------------------------------------------------------------
// Prep: activations -> fp16 (blocks [0, CONV_BLOCKS)),
//       weights -> fp16 interleaved + bias (rest)
// ---------------------------------------------------------------------------
__global__ void prep(const float* __restrict__ X, const float* __restrict__ H,
                     const float* __restrict__ U, const float* __restrict__ W,
                     const float* __restrict__ bU, const float* __restrict__ bW) {
    if (blockIdx.x < CONV_BLOCKS) {
        size_t idx = (size_t)blockIdx.x * blockDim.x + threadIdx.x;
        size_t e = idx * 4;
        size_t b = e / KTOT;
        int k = (int)(e - b * KTOT);
        float4 v;
        if (k < DIN) v = *(const float4*)(X + b * DIN + k);
        else         v = *(const float4*)(H + b * HDIM + (k - DIN));
        __half2 lo = __floats2half2_rn(v.x, v.y);
        __half2 hi = __floats2half2_rn(v.z, v.w);
        *(uint2*)(g_Apack + e) = make_uint2(*(uint32_t*)&lo, *(uint32_t*)&hi);
    } else {
        int idx = (blockIdx.x - CONV_BLOCKS) * blockDim.x + threadIdx.x;
        const int total = KTOT * HDIM;
        if (idx < total) {
            int k = idx / HDIM;
            int h = idx - k * HDIM;
            #pragma unroll
            for (int g = 0; g < 4; g++) {
                float v = (k < DIN) ? U[((size_t)g * DIN + k) * HDIM + h]
                                    : W[((size_t)g * HDIM + (k - DIN)) * HDIM + h];
                g_Bp[(size_t)(h * 4 + g) * KTOT + k] = __float2half_rn(v);
            }
        }
        if (idx < NTOT) {
            int h = idx >> 2, g = idx & 3;
            g_bias[idx] = bU[g * HDIM + h] + bW[g * HDIM + h];
        }
    }
}

// ---------------------------------------------------------------------------
// Main fused GEMM (128 threads / CTA)
// ---------------------------------------------------------------------------
__device__ __forceinline__ void load_chunk(int kc, int s, uint32_t sb,
                                           int mtile, int n0) {
    const int tid = threadIdx.x;
    const uint32_t a_base = sb + SM_AB + s * STAGE_BYTES;
    const uint32_t b_base = a_base + A_BYTES;
    // A: 128 rows x 4 x 16B = 512 ops (4 per thread)
    #pragma unroll
    for (int i = 0; i < 4; i++) {
        int op = tid + i * 128;
        int r = op >> 2, seg = op & 3;
        const __half* g = g_Apack + (size_t)(mtile * BM + r) * KTOT + kc * BK + seg * 8;
        cp16(a_base + r * ROWB + seg * 16, g);
    }
    // B: 128 rows x 4 x 16B = 512 ops (4 per thread)
    #pragma unroll
    for (int i = 0; i < 4; i++) {
        int op = tid + i * 128;
        int r = op >> 2, seg = op & 3;
        const __half* g = g_Bp + (size_t)(n0 + r) * KTOT + kc * BK + seg * 8;
        cp16(b_base + r * ROWB + seg * 16, g);
    }
}

__global__ void __launch_bounds__(128, 3)
lstm_gemm(const float* __restrict__ Cold, float* __restrict__ out) {
    extern __shared__ char smem[];
    const uint32_t sb = smem_u32(smem);
    const int tid = threadIdx.x;
    const int wid = tid >> 5, lane = tid & 31;
    const int g8 = lane >> 2, tg = lane & 3;
    const int ntile = blockIdx.x & 15;          // 16 consecutive CTAs share A
    const int mtile = blockIdx.x >> 4;
    const int n0 = ntile * BN;

    // warp grid 2(M) x 2(N); warp tile 64 x 64
    const int wm = wid & 1;                     // rows wm*64
    const int wn = wid >> 1;                    // cols wn*64

    // per-thread fragment row/col offsets (precomputed once)
    const uint32_t a_row_off = (wm * 64 + (lane & 7) + ((lane >> 3) & 1) * 8) * ROWB
                             + ((lane >> 4) & 1) * 16;
    const uint32_t b_row_off = (wn * 64 + (lane & 7) + ((lane >> 4) & 1) * 8) * ROWB
                             + ((lane >> 3) & 1) * 16;

    ((float*)(smem + SM_BIAS))[tid] = g_bias[n0 + tid];

    float acc[4][8][4];
    #pragma unroll
    for (int mt = 0; mt < 4; mt++)
        #pragma unroll
        for (int j = 0; j < 8; j++)
            #pragma unroll
            for (int q = 0; q < 4; q++) acc[mt][j][q] = 0.f;

    #pragma unroll
    for (int kc = 0; kc < STAGES - 1; kc++) {
        load_chunk(kc, kc, sb, mtile, n0);
        asm volatile("cp.async.commit_group;");
    }

    #pragma unroll 1
    for (int kc = 0; kc < NCH; kc++) {
        asm volatile("cp.async.wait_group 1;");
        __syncthreads();

        if (kc + STAGES - 1 < NCH)
            load_chunk(kc + STAGES - 1, (kc + STAGES - 1) % STAGES, sb, mtile, n0);
        asm volatile("cp.async.commit_group;");

        const int s = kc % STAGES;
        const uint32_t a_base = sb + SM_AB + s * STAGE_BYTES;
        const uint32_t b_base = a_base + A_BYTES;

        #pragma unroll
        for (int ks = 0; ks < 2; ks++) {
            const uint32_t kb = ks * 32;
            // prefetch jp=0 B slice first (its latency hides under A issue)
            uint32_t bcur[4], bnxt[4];
            LDSM4(bcur[0], bcur[1], bcur[2], bcur[3], b_base + b_row_off + kb);

            uint32_t af[4][4];
            #pragma unroll
            for (int mt = 0; mt < 4; mt++)
                LDSM4(af[mt][0], af[mt][1], af[mt][2], af[mt][3],
                      a_base + a_row_off + mt * (16 * ROWB) + kb);

            #pragma unroll
            for (int jp = 0; jp < 4; jp++) {
                if (jp < 3)
                    LDSM4(bnxt[0], bnxt[1], bnxt[2], bnxt[3],
                          b_base + b_row_off + (jp + 1) * (16 * ROWB) + kb);
                #pragma unroll
                for (int mt = 0; mt < 4; mt++) {
                    mma16816(acc[mt][2 * jp],     af[mt], bcur + 0);
                    mma16816(acc[mt][2 * jp + 1], af[mt], bcur + 2);
                }
                #pragma unroll
                for (int q = 0; q < 4; q++) bcur[q] = bnxt[q];
            }
        }
    }

    // ---------------- epilogue ----------------
    __syncthreads();                            // stage smem now free

    // stage Cold coalesced: 128 rows x 32 h-cols (this ntile covers 32 h)
    const float* cg = Cold + (size_t)(mtile * BM) * HDIM + ntile * 32;
    #pragma unroll
    for (int i = 0; i < 8; i++) {
        int idx = tid + i * 128;
        int row = idx >> 3, c4 = idx & 7;
        float4 v = *(const float4*)(cg + (size_t)row * HDIM + c4 * 4);
        *(float4*)(smem + CB_OFF + (row * ROWE + c4 * 4) * 4) = v;
    }
    __syncthreads();

    float* cb = (float*)(smem + CB_OFF);
    float* hb = (float*)(smem + HB_OFF);
    const float4* sbias4 = (const float4*)(smem + SM_BIAS);
    const int odd = tg & 1;

    #pragma unroll
    for (int mt = 0; mt < 4; mt++) {
        #pragma unroll
        for (int j = 0; j < 8; j++) {
            float c0 = acc[mt][j][0], c1 = acc[mt][j][1];
            float c2 = acc[mt][j][2], c3 = acc[mt][j][3];
            float e0 = __shfl_xor_sync(0xffffffffu, c0, 1);
            float e1 = __shfl_xor_sync(0xffffffffu, c1, 1);
            float e2 = __shfl_xor_sync(0xffffffffu, c2, 1);
            float e3 = __shfl_xor_sync(0xffffffffu, c3, 1);
            // even lane: row g8, gates (c0,c1,e0,e1); odd: row g8+8, (e2,e3,c2,c3)
            float gi = odd ? e2 : c0;
            float gf = odd ? e3 : c1;
            float go = odd ? c2 : e0;
            float gc = odd ? c3 : e1;
            int row = wm * 64 + mt * 16 + g8 + (odd ? 8 : 0);
            int hl = wn * 16 + 2 * j + (tg >> 1);
            float4 bb = sbias4[hl];
            float cold = cb[row * ROWE + hl];
            float it = sigmoid_fast(gi + bb.x);
            float ft = sigmoid_fast(gf + bb.y);
            float ot = sigmoid_fast(go + bb.z);
            float ct = tanh_fast(gc + bb.w);
            float cn = fmaf(it, ct, ft * cold);
            float hn = ot * tanh_fast(cn);
            cb[row * ROWE + hl] = cn;
            hb[row * ROWE + hl] = hn;
        }
    }
    __syncthreads();

    // coalesced writeback
    float* oh = out + (size_t)(mtile * BM) * HDIM + ntile * 32;
    float* oc = oh + (size_t)BDIM * HDIM;
    #pragma unroll
    for (int i = 0; i < 8; i++) {
        int idx = tid + i * 128;
        int row = idx >> 3, c4 = idx & 7;
        *(float4*)(oh + (size_t)row * HDIM + c4 * 4) =
            *(const float4*)(smem + HB_OFF + (row * ROWE + c4 * 4) * 4);
        *(float4*)(oc + (size_t)row * HDIM + c4 * 4) =
            *(const float4*)(smem + CB_OFF + (row * ROWE + c4 * 4) * 4);
    }
}

// ---------------------------------------------------------------------------
extern "C" void kernel_launch(void* const* d_in, const int* in_sizes, int n_in,
                              void* d_out, int out_size) {
    const float* X    = (const float*)d_in[0];
    const float* Hold = (const float*)d_in[1];
    const float* Cold = (const float*)d_in[2];
    const float* U    = (const float*)d_in[3];
    const float* bU   = (const float*)d_in[4];
    const float* W    = (const float*)d_in[5];
    const float* bW   = (const float*)d_in[6];
    float* out = (float*)d_out;
    (void)in_sizes; (void)n_in; (void)out_size;

    cudaFuncSetAttribute(lstm_gemm, cudaFuncAttributeMaxDynamicSharedMemorySize, SM_TOTAL);

    prep<<<CONV_BLOCKS + PACK_BLOCKS, 256>>>(X, Hold, U, W, bU, bW);

    const int grid = (BDIM / BM) * (NTOT / BN);   // 512 * 16 = 8192
    lstm_gemm<<<grid, 128, SM_TOTAL>>>(Cold, out);
}

// round 13
// speedup vs baseline: 1.1568x; 1.1568x over previous
#include <cuda_runtime.h>
#include <cuda_fp16.h>
#include <cstdint>

// ---------------------------------------------------------------------------
// LSTM cell, fused, sm_103 plain target (no tcgen05).
// R13: barrier-frequency fix — BK=64 (12 chunks, was 24) with a 2-stage
// cp.async pipeline; same proven geometry as R8/R12 (CTA 128x128, 4 warps of
// 64x64, 3 CTAs/SM, ldmatrix fragments, fused LSTM epilogue).
//   A[b,k]  = fp16([X | h_old])   [65536, 768]
//   Bp[n,k] = fp16 packed, n=4h+g (gates interleaved along N)
//   G = A @ Bp^T  fp32 accum  ->  gates -> h_new, c_new
// ---------------------------------------------------------------------------

#define BDIM 65536
#define HDIM 512
#define DIN  256
#define NTOT 2048
#define KTOT 768

#define BM 128
#define BN 128
#define BK 64
#define STAGES 2
#define NCH (KTOT / BK)            // 12

#define ROWB 144                   // 64 fp16 = 128B + 16B pad (9 units, coprime 8)
#define A_BYTES (BM * ROWB)        // 18432
#define B_BYTES (BN * ROWB)        // 18432
#define STAGE_BYTES (A_BYTES + B_BYTES)           // 36864
#define SM_BIAS 0                                  // 512 B used
#define SM_AB   1024
#define SM_TOTAL (SM_AB + STAGES * STAGE_BYTES)    // 74752 (x3 CTAs = 224KB)

// epilogue overlay (stage area free by then): 128 rows x 32 h-cols, pad to 36
#define ROWE 36
#define HB_OFF SM_AB
#define CB_OFF (SM_AB + BM * ROWE * 4)             // 1024 + 18432

#define CONV_BLOCKS 49152
#define PACK_BLOCKS 1536

__device__ __half g_Apack[(size_t)BDIM * KTOT];    // 96 MB
__device__ __half g_Bp[(size_t)NTOT * KTOT];       // 3 MB
__device__ float  g_bias[NTOT];

// ---------------------------------------------------------------------------
__device__ __forceinline__ uint32_t smem_u32(const void* p) {
    uint32_t a;
    asm("{ .reg .u64 t; cvta.to.shared.u64 t, %1; cvt.u32.u64 %0, t; }"
        : "=r"(a) : "l"(p));
    return a;
}
__device__ __forceinline__ void cp16(uint32_t sa, const void* g) {
    asm volatile("cp.async.cg.shared.global [%0], [%1], 16;" :: "r"(sa), "l"(g));
}
#define LDSM4(r0, r1, r2, r3, a)                                              \
    asm volatile("ldmatrix.sync.aligned.m8n8.x4.shared.b16 {%0,%1,%2,%3}, [%4];" \
        : "=r"(r0), "=r"(r1), "=r"(r2), "=r"(r3) : "r"(a))

__device__ __forceinline__ void mma16816(float* c, const uint32_t* a, const uint32_t* b) {
    asm volatile(
        "mma.sync.aligned.m16n8k16.row.col.f32.f16.f16.f32 "
        "{%0,%1,%2,%3}, {%4,%5,%6,%7}, {%8,%9}, {%0,%1,%2,%3};"
        : "+f"(c[0]), "+f"(c[1]), "+f"(c[2]), "+f"(c[3])
        : "r"(a[0]), "r"(a[1]), "r"(a[2]), "r"(a[3]), "r"(b[0]), "r"(b[1]));
}
__device__ __forceinline__ float tanh_fast(float x) {
    float y;
    asm("tanh.approx.f32 %0, %1;" : "=f"(y) : "f"(x));
    return y;
}
__device__ __forceinline__ float sigmoid_fast(float x) {
    return fmaf(0.5f, tanh_fast(0.5f * x), 0.5f);
}

// ---------------------------------------------------------------------------
// Prep: activations -> fp16 (blocks [0, CONV_BLOCKS)),
//       weights -> fp16 interleaved + bias (rest)
// ---------------------------------------------------------------------------
__global__ void prep(const float* __restrict__ X, const float* __restrict__ H,
                     const float* __restrict__ U, const float* __restrict__ W,
                     const float* __restrict__ bU, const float* __restrict__ bW) {
    if (blockIdx.x < CONV_BLOCKS) {
        size_t idx = (size_t)blockIdx.x * blockDim.x + threadIdx.x;
        size_t e = idx * 4;
        size_t b = e / KTOT;
        int k = (int)(e - b * KTOT);
        float4 v;
        if (k < DIN) v = *(const float4*)(X + b * DIN + k);
        else         v = *(const float4*)(H + b * HDIM + (k - DIN));
        __half2 lo = __floats2half2_rn(v.x, v.y);
        __half2 hi = __floats2half2_rn(v.z, v.w);
        *(uint2*)(g_Apack + e) = make_uint2(*(uint32_t*)&lo, *(uint32_t*)&hi);
    } else {
        int idx = (blockIdx.x - CONV_BLOCKS) * blockDim.x + threadIdx.x;
        const int total = KTOT * HDIM;
        if (idx < total) {
            int k = idx / HDIM;
            int h = idx - k * HDIM;
            #pragma unroll
            for (int g = 0; g < 4; g++) {
                float v = (k < DIN) ? U[((size_t)g * DIN + k) * HDIM + h]
                                    : W[((size_t)g * HDIM + (k - DIN)) * HDIM + h];
                g_Bp[(size_t)(h * 4 + g) * KTOT + k] = __float2half_rn(v);
            }
        }
        if (idx < NTOT) {
            int h = idx >> 2, g = idx & 3;
            g_bias[idx] = bU[g * HDIM + h] + bW[g * HDIM + h];
        }
    }
}

// ---------------------------------------------------------------------------
// Main fused GEMM (128 threads / CTA)
// ---------------------------------------------------------------------------
__device__ __forceinline__ void load_chunk(int kc, int s, uint32_t sb,
                                           int mtile, int n0) {
    const int tid = threadIdx.x;
    const uint32_t a_base = sb + SM_AB + s * STAGE_BYTES;
    const uint32_t b_base = a_base + A_BYTES;
    // A: 128 rows x 8 x 16B = 1024 ops (8 per thread)
    #pragma unroll
    for (int i = 0; i < 8; i++) {
        int op = tid + i * 128;
        int r = op >> 3, seg = op & 7;
        const __half* g = g_Apack + (size_t)(mtile * BM + r) * KTOT + kc * BK + seg * 8;
        cp16(a_base + r * ROWB + seg * 16, g);
    }
    // B: 128 rows x 8 x 16B = 1024 ops (8 per thread)
    #pragma unroll
    for (int i = 0; i < 8; i++) {
        int op = tid + i * 128;
        int r = op >> 3, seg = op & 7;
        const __half* g = g_Bp + (size_t)(n0 + r) * KTOT + kc * BK + seg * 8;
        cp16(b_base + r * ROWB + seg * 16, g);
    }
}

__global__ void __launch_bounds__(128, 3)
lstm_gemm(const float* __restrict__ Cold, float* __restrict__ out) {
    extern __shared__ char smem[];
    const uint32_t sb = smem_u32(smem);
    const int tid = threadIdx.x;
    const int wid = tid >> 5, lane = tid & 31;
    const int g8 = lane >> 2, tg = lane & 3;
    const int ntile = blockIdx.x & 15;          // 16 consecutive CTAs share A
    const int mtile = blockIdx.x >> 4;
    const int n0 = ntile * BN;

    // warp grid 2(M) x 2(N); warp tile 64 x 64
    const int wm = wid & 1;                     // rows wm*64
    const int wn = wid >> 1;                    // cols wn*64

    // per-thread fragment row/col offsets (precomputed once)
    const uint32_t a_row_off = (wm * 64 + (lane & 7) + ((lane >> 3) & 1) * 8) * ROWB
                             + ((lane >> 4) & 1) * 16;
    const uint32_t b_row_off = (wn * 64 + (lane & 7) + ((lane >> 4) & 1) * 8) * ROWB
                             + ((lane >> 3) & 1) * 16;

    ((float*)(smem + SM_BIAS))[tid] = g_bias[n0 + tid];

    float acc[4][8][4];
    #pragma unroll
    for (int mt = 0; mt < 4; mt++)
        #pragma unroll
        for (int j = 0; j < 8; j++)
            #pragma unroll
            for (int q = 0; q < 4; q++) acc[mt][j][q] = 0.f;

    // prologue: stage 0 = chunk 0
    load_chunk(0, 0, sb, mtile, n0);
    asm volatile("cp.async.commit_group;");

    #pragma unroll 1
    for (int kc = 0; kc < NCH; kc++) {
        // chunk kc's loads complete (it is the only pending group here)
        asm volatile("cp.async.wait_group 0;");
        __syncthreads();
        // buffer (kc+1)&1 was consumed in compute(kc-1), finished before the
        // barrier above -> safe to refill now; its latency hides under compute(kc)
        if (kc + 1 < NCH)
            load_chunk(kc + 1, (kc + 1) & 1, sb, mtile, n0);
        asm volatile("cp.async.commit_group;");

        const uint32_t a_base = sb + SM_AB + (kc & 1) * STAGE_BYTES;
        const uint32_t b_base = a_base + A_BYTES;

        #pragma unroll
        for (int ks = 0; ks < 4; ks++) {
            const uint32_t kb = ks * 32;
            // prefetch jp=0 B slice first (its latency hides under A issue)
            uint32_t bcur[4], bnxt[4];
            LDSM4(bcur[0], bcur[1], bcur[2], bcur[3], b_base + b_row_off + kb);

            uint32_t af[4][4];
            #pragma unroll
            for (int mt = 0; mt < 4; mt++)
                LDSM4(af[mt][0], af[mt][1], af[mt][2], af[mt][3],
                      a_base + a_row_off + mt * (16 * ROWB) + kb);

            #pragma unroll
            for (int jp = 0; jp < 4; jp++) {
                if (jp < 3)
                    LDSM4(bnxt[0], bnxt[1], bnxt[2], bnxt[3],
                          b_base + b_row_off + (jp + 1) * (16 * ROWB) + kb);
                #pragma unroll
                for (int mt = 0; mt < 4; mt++) {
                    mma16816(acc[mt][2 * jp],     af[mt], bcur + 0);
                    mma16816(acc[mt][2 * jp + 1], af[mt], bcur + 2);
                }
                #pragma unroll
                for (int q = 0; q < 4; q++) bcur[q] = bnxt[q];
            }
        }
    }

    // ---------------- epilogue ----------------
    __syncthreads();                            // stage smem now free

    // stage Cold coalesced: 128 rows x 32 h-cols (this ntile covers 32 h)
    const float* cg = Cold + (size_t)(mtile * BM) * HDIM + ntile * 32;
    #pragma unroll
    for (int i = 0; i < 8; i++) {
        int idx = tid + i * 128;
        int row = idx >> 3, c4 = idx & 7;
        float4 v = *(const float4*)(cg + (size_t)row * HDIM + c4 * 4);
        *(float4*)(smem + CB_OFF + (row * ROWE + c4 * 4) * 4) = v;
    }
    __syncthreads();

    float* cb = (float*)(smem + CB_OFF);
    float* hb = (float*)(smem + HB_OFF);
    const float4* sbias4 = (const float4*)(smem + SM_BIAS);
    const int odd = tg & 1;

    #pragma unroll
    for (int mt = 0; mt < 4; mt++) {
        #pragma unroll
        for (int j = 0; j < 8; j++) {
            float c0 = acc[mt][j][0], c1 = acc[mt][j][1];
            float c2 = acc[mt][j][2], c3 = acc[mt][j][3];
            float e0 = __shfl_xor_sync(0xffffffffu, c0, 1);
            float e1 = __shfl_xor_sync(0xffffffffu, c1, 1);
            float e2 = __shfl_xor_sync(0xffffffffu, c2, 1);
            float e3 = __shfl_xor_sync(0xffffffffu, c3, 1);
            // even lane: row g8, gates (c0,c1,e0,e1); odd: row g8+8, (e2,e3,c2,c3)
            float gi = odd ? e2 : c0;
            float gf = odd ? e3 : c1;
            float go = odd ? c2 : e0;
            float gc = odd ? c3 : e1;
            int row = wm * 64 + mt * 16 + g8 + (odd ? 8 : 0);
            int hl = wn * 16 + 2 * j + (tg >> 1);
            float4 bb = sbias4[hl];
            float cold = cb[row * ROWE + hl];
            float it = sigmoid_fast(gi + bb.x);
            float ft = sigmoid_fast(gf + bb.y);
            float ot = sigmoid_fast(go + bb.z);
            float ct = tanh_fast(gc + bb.w);
            float cn = fmaf(it, ct, ft * cold);
            float hn = ot * tanh_fast(cn);
            cb[row * ROWE + hl] = cn;
            hb[row * ROWE + hl] = hn;
        }
    }
    __syncthreads();

    // coalesced writeback
    float* oh = out + (size_t)(mtile * BM) * HDIM + ntile * 32;
    float* oc = oh + (size_t)BDIM * HDIM;
    #pragma unroll
    for (int i = 0; i < 8; i++) {
        int idx = tid + i * 128;
        int row = idx >> 3, c4 = idx & 7;
        *(float4*)(oh + (size_t)row * HDIM + c4 * 4) =
            *(const float4*)(smem + HB_OFF + (row * ROWE + c4 * 4) * 4);
        *(float4*)(oc + (size_t)row * HDIM + c4 * 4) =
            *(const float4*)(smem + CB_OFF + (row * ROWE + c4 * 4) * 4);
    }
}

// ---------------------------------------------------------------------------
extern "C" void kernel_launch(void* const* d_in, const int* in_sizes, int n_in,
                              void* d_out, int out_size) {
    const float* X    = (const float*)d_in[0];
    const float* Hold = (const float*)d_in[1];
    const float* Cold = (const float*)d_in[2];
    const float* U    = (const float*)d_in[3];
    const float* bU   = (const float*)d_in[4];
    const float* W    = (const float*)d_in[5];
    const float* bW   = (const float*)d_in[6];
    float* out = (float*)d_out;
    (void)in_sizes; (void)n_in; (void)out_size;

    cudaFuncSetAttribute(lstm_gemm, cudaFuncAttributeMaxDynamicSharedMemorySize, SM_TOTAL);

    prep<<<CONV_BLOCKS + PACK_BLOCKS, 256>>>(X, Hold, U, W, bU, bW);

    const int grid = (BDIM / BM) * (NTOT / BN);   // 512 * 16 = 8192
    lstm_gemm<<<grid, 128, SM_TOTAL>>>(Cold, out);
}

// round 14
// speedup vs baseline: 1.1663x; 1.0083x over previous
#include <cuda_runtime.h>
#include <cuda_fp16.h>
#include <cstdint>

// ---------------------------------------------------------------------------
// LSTM cell, fused, sm_103 plain target (no tcgen05).
// R14: convoy elimination — per-chunk full-CTA rendezvous (wait_group +
// __syncthreads) replaced by mbarrier producer/consumer pairs:
//   full[b]  : cp.async.mbarrier.arrive.noinc (data arrival, count=128)
//   empty[b] : release-arrive after compute -> acquire-wait before buffer reuse
// Warps now decouple with one-chunk slack instead of re-converging 12x.
// Geometry unchanged from R13: CTA 128x128, 4 warps of 64x64, BK=64,
// 2 stages, 3 CTAs/SM, ldmatrix fragments, fused LSTM epilogue.
//   A[b,k]  = fp16([X | h_old])   [65536, 768]
//   Bp[n,k] = fp16 packed, n=4h+g (gates interleaved along N)
//   G = A @ Bp^T  fp32 accum  ->  gates -> h_new, c_new
// ---------------------------------------------------------------------------

#define BDIM 65536
#define HDIM 512
#define DIN  256
#define NTOT 2048
#define KTOT 768

#define BM 128
#define BN 128
#define BK 64
#define NCH (KTOT / BK)            // 12

#define ROWB 144                   // 64 fp16 = 128B + 16B pad (9 units, coprime 8)
#define A_BYTES (BM * ROWB)        // 18432
#define B_BYTES (BN * ROWB)        // 18432
#define STAGE_BYTES (A_BYTES + B_BYTES)           // 36864
#define SM_BIAS 0                                  // 512 B
#define SM_MBAR 512                                // full[0],full[1],empty[0],empty[1]
#define SM_AB   1024
#define SM_TOTAL (SM_AB + 2 * STAGE_BYTES)         // 74752 (x3 CTAs = 224KB)

// epilogue overlay (stage area free by then): 128 rows x 32 h-cols, pad to 36
#define ROWE 36
#define HB_OFF SM_AB
#define CB_OFF (SM_AB + BM * ROWE * 4)             // 1024 + 18432

#define CONV_BLOCKS 49152
#define PACK_BLOCKS 1536

__device__ __half g_Apack[(size_t)BDIM * KTOT];    // 96 MB
__device__ __half g_Bp[(size_t)NTOT * KTOT];       // 3 MB
__device__ float  g_bias[NTOT];

// ---------------------------------------------------------------------------
__device__ __forceinline__ uint32_t smem_u32(const void* p) {
    uint32_t a;
    asm("{ .reg .u64 t; cvta.to.shared.u64 t, %1; cvt.u32.u64 %0, t; }"
        : "=r"(a) : "l"(p));
    return a;
}
__device__ __forceinline__ void cp16(uint32_t sa, const void* g) {
    asm volatile("cp.async.cg.shared.global [%0], [%1], 16;" :: "r"(sa), "l"(g));
}
#define LDSM4(r0, r1, r2, r3, a)                                              \
    asm volatile("ldmatrix.sync.aligned.m8n8.x4.shared.b16 {%0,%1,%2,%3}, [%4];" \
        : "=r"(r0), "=r"(r1), "=r"(r2), "=r"(r3) : "r"(a))

__device__ __forceinline__ void mma16816(float* c, const uint32_t* a, const uint32_t* b) {
    asm volatile(
        "mma.sync.aligned.m16n8k16.row.col.f32.f16.f16.f32 "
        "{%0,%1,%2,%3}, {%4,%5,%6,%7}, {%8,%9}, {%0,%1,%2,%3};"
        : "+f"(c[0]), "+f"(c[1]), "+f"(c[2]), "+f"(c[3])
        : "r"(a[0]), "r"(a[1]), "r"(a[2]), "r"(a[3]), "r"(b[0]), "r"(b[1]));
}
__device__ __forceinline__ float tanh_fast(float x) {
    float y;
    asm("tanh.approx.f32 %0, %1;" : "=f"(y) : "f"(x));
    return y;
}
__device__ __forceinline__ float sigmoid_fast(float x) {
    return fmaf(0.5f, tanh_fast(0.5f * x), 0.5f);
}

// ---- mbarrier helpers (plain sm_90-level PTX; legal at compute_103) ----
#define MBAR_INIT(addr, cnt) \
    asm volatile("mbarrier.init.shared.b64 [%0], %1;" :: "r"(addr), "r"(cnt) : "memory")
#define MBAR_ARRIVE(addr) \
    asm volatile("mbarrier.arrive.release.cta.shared::cta.b64 _, [%0];" :: "r"(addr) : "memory")
#define CPASYNC_MBAR_ARRIVE(addr) \
    asm volatile("cp.async.mbarrier.arrive.noinc.shared::cta.b64 [%0];" :: "r"(addr) : "memory")
#define MBAR_WAIT(addr, parity) do {                                          \
    uint32_t _m = (addr), _p = (parity), _d;                                  \
    asm volatile("{\n\t.reg .pred p;\n\t"                                     \
        "mbarrier.try_wait.parity.acquire.cta.shared::cta.b64 p, [%1], %2;\n\t"\
        "selp.b32 %0, 1, 0, p;\n\t}" : "=r"(_d) : "r"(_m), "r"(_p) : "memory");\
    if (!_d) {                                                                \
        asm volatile("{\n\t.reg .pred P1;\n\t"                                \
            "WL_%=:\n\t"                                                      \
            "mbarrier.try_wait.parity.acquire.cta.shared::cta.b64 P1, [%0], %1, 0x989680;\n\t" \
            "@P1 bra.uni WD_%=;\n\t"                                          \
            "bra.uni WL_%=;\n\t"                                              \
            "WD_%=:\n\t}" :: "r"(_m), "r"(_p) : "memory");                    \
    }                                                                         \
} while (0)

// ---------------------------------------------------------------------------
// Prep: activations -> fp16 (blocks [0, CONV_BLOCKS)),
//       weights -> fp16 interleaved + bias (rest)
// ---------------------------------------------------------------------------
__global__ void prep(const float* __restrict__ X, const float* __restrict__ H,
                     const float* __restrict__ U, const float* __restrict__ W,
                     const float* __restrict__ bU, const float* __restrict__ bW) {
    if (blockIdx.x < CONV_BLOCKS) {
        size_t idx = (size_t)blockIdx.x * blockDim.x + threadIdx.x;
        size_t e = idx * 4;
        size_t b = e / KTOT;
        int k = (int)(e - b * KTOT);
        float4 v;
        if (k < DIN) v = *(const float4*)(X + b * DIN + k);
        else         v = *(const float4*)(H + b * HDIM + (k - DIN));
        __half2 lo = __floats2half2_rn(v.x, v.y);
        __half2 hi = __floats2half2_rn(v.z, v.w);
        *(uint2*)(g_Apack + e) = make_uint2(*(uint32_t*)&lo, *(uint32_t*)&hi);
    } else {
        int idx = (blockIdx.x - CONV_BLOCKS) * blockDim.x + threadIdx.x;
        const int total = KTOT * HDIM;
        if (idx < total) {
            int k = idx / HDIM;
            int h = idx - k * HDIM;
            #pragma unroll
            for (int g = 0; g < 4; g++) {
                float v = (k < DIN) ? U[((size_t)g * DIN + k) * HDIM + h]
                                    : W[((size_t)g * HDIM + (k - DIN)) * HDIM + h];
                g_Bp[(size_t)(h * 4 + g) * KTOT + k] = __float2half_rn(v);
            }
        }
        if (idx < NTOT) {
            int h = idx >> 2, g = idx & 3;
            g_bias[idx] = bU[g * HDIM + h] + bW[g * HDIM + h];
        }
    }
}

// ---------------------------------------------------------------------------
// Main fused GEMM (128 threads / CTA)
// ---------------------------------------------------------------------------
__device__ __forceinline__ void load_chunk(int kc, int s, uint32_t sb,
                                           int mtile, int n0) {
    const int tid = threadIdx.x;
    const uint32_t a_base = sb + SM_AB + s * STAGE_BYTES;
    const uint32_t b_base = a_base + A_BYTES;
    // A: 128 rows x 8 x 16B = 1024 ops (8 per thread)
    #pragma unroll
    for (int i = 0; i < 8; i++) {
        int op = tid + i * 128;
        int r = op >> 3, seg = op & 7;
        const __half* g = g_Apack + (size_t)(mtile * BM + r) * KTOT + kc * BK + seg * 8;
        cp16(a_base + r * ROWB + seg * 16, g);
    }
    // B: 128 rows x 8 x 16B = 1024 ops (8 per thread)
    #pragma unroll
    for (int i = 0; i < 8; i++) {
        int op = tid + i * 128;
        int r = op >> 3, seg = op & 7;
        const __half* g = g_Bp + (size_t)(n0 + r) * KTOT + kc * BK + seg * 8;
        cp16(b_base + r * ROWB + seg * 16, g);
    }
}

__global__ void __launch_bounds__(128, 3)
lstm_gemm(const float* __restrict__ Cold, float* __restrict__ out) {
    extern __shared__ char smem[];
    const uint32_t sb = smem_u32(smem);
    const int tid = threadIdx.x;
    const int wid = tid >> 5, lane = tid & 31;
    const int g8 = lane >> 2, tg = lane & 3;
    const int ntile = blockIdx.x & 15;          // 16 consecutive CTAs share A
    const int mtile = blockIdx.x >> 4;
    const int n0 = ntile * BN;

    // warp grid 2(M) x 2(N); warp tile 64 x 64
    const int wm = wid & 1;                     // rows wm*64
    const int wn = wid >> 1;                    // cols wn*64

    const uint32_t a_row_off = (wm * 64 + (lane & 7) + ((lane >> 3) & 1) * 8) * ROWB
                             + ((lane >> 4) & 1) * 16;
    const uint32_t b_row_off = (wn * 64 + (lane & 7) + ((lane >> 4) & 1) * 8) * ROWB
                             + ((lane >> 3) & 1) * 16;

    const uint32_t mb_full  = sb + SM_MBAR;      // +0, +8
    const uint32_t mb_empty = sb + SM_MBAR + 16; // +0, +8

    if (tid == 0) {
        MBAR_INIT(mb_full + 0, 128);
        MBAR_INIT(mb_full + 8, 128);
        MBAR_INIT(mb_empty + 0, 128);
        MBAR_INIT(mb_empty + 8, 128);
    }
    ((float*)(smem + SM_BIAS))[tid] = g_bias[n0 + tid];
    __syncthreads();

    float acc[4][8][4];
    #pragma unroll
    for (int mt = 0; mt < 4; mt++)
        #pragma unroll
        for (int j = 0; j < 8; j++)
            #pragma unroll
            for (int q = 0; q < 4; q++) acc[mt][j][q] = 0.f;

    // prologue: chunk 0 -> buffer 0, signal full[0] on completion
    load_chunk(0, 0, sb, mtile, n0);
    CPASYNC_MBAR_ARRIVE(mb_full + 0);

    #pragma unroll 1
    for (int kc = 0; kc < NCH; kc++) {
        const int nb = (kc + 1) & 1;
        if (kc + 1 < NCH) {
            // buffer nb was read by compute(kc-1); wait its empty-release
            if (kc >= 1)
                MBAR_WAIT(mb_empty + nb * 8, (uint32_t)(((kc - 1) >> 1) & 1));
            load_chunk(kc + 1, nb, sb, mtile, n0);
            CPASYNC_MBAR_ARRIVE(mb_full + nb * 8);
        }
        // wait chunk kc's data (arrivals from every thread's cp.async batch)
        MBAR_WAIT(mb_full + (kc & 1) * 8, (uint32_t)((kc >> 1) & 1));

        const uint32_t a_base = sb + SM_AB + (kc & 1) * STAGE_BYTES;
        const uint32_t b_base = a_base + A_BYTES;

        #pragma unroll
        for (int ks = 0; ks < 4; ks++) {
            const uint32_t kb = ks * 32;
            uint32_t bcur[4], bnxt[4];
            LDSM4(bcur[0], bcur[1], bcur[2], bcur[3], b_base + b_row_off + kb);

            uint32_t af[4][4];
            #pragma unroll
            for (int mt = 0; mt < 4; mt++)
                LDSM4(af[mt][0], af[mt][1], af[mt][2], af[mt][3],
                      a_base + a_row_off + mt * (16 * ROWB) + kb);

            #pragma unroll
            for (int jp = 0; jp < 4; jp++) {
                if (jp < 3)
                    LDSM4(bnxt[0], bnxt[1], bnxt[2], bnxt[3],
                          b_base + b_row_off + (jp + 1) * (16 * ROWB) + kb);
                #pragma unroll
                for (int mt = 0; mt < 4; mt++) {
                    mma16816(acc[mt][2 * jp],     af[mt], bcur + 0);
                    mma16816(acc[mt][2 * jp + 1], af[mt], bcur + 2);
                }
                #pragma unroll
                for (int q = 0; q < 4; q++) bcur[q] = bnxt[q];
            }
        }
        // done reading buffer kc&1
        MBAR_ARRIVE(mb_empty + (kc & 1) * 8);
    }

    // ---------------- epilogue ----------------
    __syncthreads();                            // all warps past mainloop; stage smem free

    // stage Cold coalesced: 128 rows x 32 h-cols (this ntile covers 32 h)
    const float* cg = Cold + (size_t)(mtile * BM) * HDIM + ntile * 32;
    #pragma unroll
    for (int i = 0; i < 8; i++) {
        int idx = tid + i * 128;
        int row = idx >> 3, c4 = idx & 7;
        float4 v = *(const float4*)(cg + (size_t)row * HDIM + c4 * 4);
        *(float4*)(smem + CB_OFF + (row * ROWE + c4 * 4) * 4) = v;
    }
    __syncthreads();

    float* cb = (float*)(smem + CB_OFF);
    float* hb = (float*)(smem + HB_OFF);
    const float4* sbias4 = (const float4*)(smem + SM_BIAS);
    const int odd = tg & 1;

    #pragma unroll
    for (int mt = 0; mt < 4; mt++) {
        #pragma unroll
        for (int j = 0; j < 8; j++) {
            float c0 = acc[mt][j][0], c1 = acc[mt][j][1];
            float c2 = acc[mt][j][2], c3 = acc[mt][j][3];
            float e0 = __shfl_xor_sync(0xffffffffu, c0, 1);
            float e1 = __shfl_xor_sync(0xffffffffu, c1, 1);
            float e2 = __shfl_xor_sync(0xffffffffu, c2, 1);
            float e3 = __shfl_xor_sync(0xffffffffu, c3, 1);
            // even lane: row g8, gates (c0,c1,e0,e1); odd: row g8+8, (e2,e3,c2,c3)
            float gi = odd ? e2 : c0;
            float gf = odd ? e3 : c1;
            float go = odd ? c2 : e0;
            float gc = odd ? c3 : e1;
            int row = wm * 64 + mt * 16 + g8 + (odd ? 8 : 0);
            int hl = wn * 16 + 2 * j + (tg >> 1);
            float4 bb = sbias4[hl];
            float cold = cb[row * ROWE + hl];
            float it = sigmoid_fast(gi + bb.x);
            float ft = sigmoid_fast(gf + bb.y);
            float ot = sigmoid_fast(go + bb.z);
            float ct = tanh_fast(gc + bb.w);
            float cn = fmaf(it, ct, ft * cold);
            float hn = ot * tanh_fast(cn);
            cb[row * ROWE + hl] = cn;
            hb[row * ROWE + hl] = hn;
        }
    }
    __syncthreads();

    // coalesced writeback
    float* oh = out + (size_t)(mtile * BM) * HDIM + ntile * 32;
    float* oc = oh + (size_t)BDIM * HDIM;
    #pragma unroll
    for (int i = 0; i < 8; i++) {
        int idx = tid + i * 128;
        int row = idx >> 3, c4 = idx & 7;
        *(float4*)(oh + (size_t)row * HDIM + c4 * 4) =
            *(const float4*)(smem + HB_OFF + (row * ROWE + c4 * 4) * 4);
        *(float4*)(oc + (size_t)row * HDIM + c4 * 4) =
            *(const float4*)(smem + CB_OFF + (row * ROWE + c4 * 4) * 4);
    }
}

// ---------------------------------------------------------------------------
extern "C" void kernel_launch(void* const* d_in, const int* in_sizes, int n_in,
                              void* d_out, int out_size) {
    const float* X    = (const float*)d_in[0];
    const float* Hold = (const float*)d_in[1];
    const float* Cold = (const float*)d_in[2];
    const float* U    = (const float*)d_in[3];
    const float* bU   = (const float*)d_in[4];
    const float* W    = (const float*)d_in[5];
    const float* bW   = (const float*)d_in[6];
    float* out = (float*)d_out;
    (void)in_sizes; (void)n_in; (void)out_size;

    cudaFuncSetAttribute(lstm_gemm, cudaFuncAttributeMaxDynamicSharedMemorySize, SM_TOTAL);

    prep<<<CONV_BLOCKS + PACK_BLOCKS, 256>>>(X, Hold, U, W, bU, bW);

    const int grid = (BDIM / BM) * (NTOT / BN);   // 512 * 16 = 8192
    lstm_gemm<<<grid, 128, SM_TOTAL>>>(Cold, out);
}